// round 11
// baseline (speedup 1.0000x reference)
#include <cuda_runtime.h>

#define NN 2048
#define FF 64
#define KK 8
#define GROUP 8
#define NGRP (NN / GROUP)     // 256 groups of 8
#define PHA 14                // phase-A groups (112 ranks), multiple of 2
#define NBUCK 4096
#define BSHIFT 20             // 32 - log2(NBUCK)
#define BPT (NBUCK / 256)

// Scratch: per-feature bucket-descending (x value, byte-offset) pairs + exact
// per-group suffix-max stop bounds.
__device__ float2 g_sp[FF * (NN + 32)];
__device__ float  g_bound[FF * NGRP];

__device__ __forceinline__ unsigned key_of(float v) {
    unsigned u = __float_as_uint(v);
    return (u & 0x80000000u) ? ~u : (u | 0x80000000u);
}
__device__ __forceinline__ float val_of(unsigned k) {
    unsigned u = (k & 0x80000000u) ? (k ^ 0x80000000u) : ~k;
    return __uint_as_float(u);
}

// One block per feature f: counting-sort rows into descending-bucket order,
// store (x value, row byte-offset) pairs + exact suffix-max stop bounds.
// (No L2 warm: R1/R5/R8 proved topk duration is invariant to adj residency —
// the kernel is issue-bound, not memory-bound.)
__global__ __launch_bounds__(256) void prep_kernel(const float* __restrict__ x) {
    const int tid = threadIdx.x;
    const int f = blockIdx.x;
    const float NEG_INF = -__int_as_float(0x7f800000);

    __shared__ unsigned skey[NN];
    __shared__ int hist[NBUCK];
    __shared__ float sval[NN];
    __shared__ int tsum[256];
    __shared__ float tmax[256];

    for (int i = tid; i < NBUCK; i += 256) hist[i] = 0;
    __syncthreads();

    // Pass 1: keys + histogram.
    for (int i = tid; i < NN; i += 256) {
        float v = x[(size_t)i * FF + f];
        unsigned k = key_of(v);
        skey[i] = k;
        atomicAdd(&hist[k >> BSHIFT], 1);
    }
    __syncthreads();

    // Pass 2: descending-exclusive bucket offsets (suffix scan).
    const int base = tid * BPT;
    int csum = 0;
    #pragma unroll
    for (int j = 0; j < BPT; j++) csum += hist[base + j];
    tsum[tid] = csum;
    __syncthreads();
    for (int d = 1; d < 256; d <<= 1) {
        int v = tsum[tid] + ((tid + d < 256) ? tsum[tid + d] : 0);
        __syncthreads();
        tsum[tid] = v;
        __syncthreads();
    }
    int run = (tid < 255) ? tsum[tid + 1] : 0;
    #pragma unroll
    for (int j = BPT - 1; j >= 0; j--) {
        int c = hist[base + j];
        hist[base + j] = run;
        run += c;
    }
    __syncthreads();

    // Pass 3: scatter (value, byte offset = idx * NN * 4).
    for (int i = tid; i < NN; i += 256) {
        unsigned k = skey[i];
        float v = val_of(k);
        int pos = atomicAdd(&hist[k >> BSHIFT], 1);
        g_sp[f * (NN + 32) + pos] = make_float2(v, __int_as_float(i * (NN * 4)));
        sval[pos] = v;
    }
    // Pad: value -inf, offset 0 (products never beat real entries; NaN from
    // 0*-inf compares false against t and is never inserted).
    for (int i = NN + tid; i < NN + 32; i += 256)
        g_sp[f * (NN + 32) + i] = make_float2(NEG_INF, __int_as_float(0));
    __syncthreads();

    // Pass 4: exact suffix-max bounds per group of 8. After group g, all
    // remaining products <= max(suffix_max(g+1), 0) since adj in [0,1).
    float gm = NEG_INF;
    #pragma unroll
    for (int j = 0; j < GROUP; j++) gm = fmaxf(gm, sval[tid * GROUP + j]);
    tmax[tid] = gm;
    __syncthreads();
    for (int d = 1; d < 256; d <<= 1) {       // inclusive suffix max
        float v = fmaxf(tmax[tid], (tid + d < 256) ? tmax[tid + d] : NEG_INF);
        __syncthreads();
        tmax[tid] = v;
        __syncthreads();
    }
    float b = (tid < 255) ? tmax[tid + 1] : NEG_INF;
    g_bound[f * NGRP + tid] = fmaxf(b, 0.0f);
}

// blockIdx.y = f, blockIdx.x = m-tile. Each thread owns TWO adjacent m
// (float2 loads): LDS/address/loop cost amortized over 2 products.
// Phase A: 112 ranks unconditional (extra inserts are always correct).
// Phase B: branchy with exact suffix-max stop bound.
__global__ __launch_bounds__(128) void topk_kernel(const float* __restrict__ x,
                                                   const float* __restrict__ adj,
                                                   float* __restrict__ out) {
    __shared__ float2 s_p[NN + 32];
    __shared__ float  s_b[NGRP];
    const int f = blockIdx.y;
    const int tid = threadIdx.x;
    const float NEG_INF = -__int_as_float(0x7f800000);

    #pragma unroll
    for (int i = tid; i < NN + 32; i += 128) s_p[i] = g_sp[f * (NN + 32) + i];
    if (tid < NGRP - 128) s_b[128 + tid] = g_bound[f * NGRP + 128 + tid];
    s_b[tid] = g_bound[f * NGRP + tid];
    __syncthreads();

    const int m0 = (blockIdx.x * 128 + tid) * 2;   // this thread's m pair
    const char* adjm = (const char*)(adj + m0);

    float ta[KK], tb[KK];
    #pragma unroll
    for (int j = 0; j < KK; j++) { ta[j] = NEG_INF; tb[j] = NEG_INF; }

    float2 ca[GROUP], cb[GROUP];

    // Load group g: product pair (adj[n][m0], adj[n][m0+1]) * x[n][f].
    #define LOADC(g, buf)                                                     \
        {   _Pragma("unroll")                                                 \
            for (int u = 0; u < GROUP; u++) {                                 \
                float2 p = s_p[(g) * GROUP + u];                              \
                const float2 a =                                              \
                    *(const float2*)(adjm + __float_as_int(p.y));             \
                buf[u].x = a.x * p.x;                                         \
                buf[u].y = a.y * p.x;                                         \
            }                                                                 \
        }
    #define INSERT(tarr, cval)                                                \
        {   float c = (cval);                                                 \
            if (c > tarr[KK - 1]) {                                           \
                _Pragma("unroll")                                             \
                for (int j = 0; j < KK - 1; j++) {                            \
                    float w = fmaxf(tarr[j], c);                              \
                    c = fminf(tarr[j], c);                                    \
                    tarr[j] = w;                                              \
                }                                                             \
                tarr[KK - 1] = fmaxf(tarr[KK - 1], c);                        \
            }                                                                 \
        }
    #define CONSUME(buf)                                                      \
        {   _Pragma("unroll")                                                 \
            for (int u = 0; u < GROUP; u++) {                                 \
                INSERT(ta, buf[u].x);                                         \
                INSERT(tb, buf[u].y);                                         \
            }                                                                 \
        }

    LOADC(0, ca); LOADC(1, cb);

    // ---- Phase A: groups 0..PHA-1, unconditional, double-buffered. ----
    #pragma unroll 1
    for (int g = 0; g < PHA; g += 2) {
        CONSUME(ca); LOADC(g + 2, ca);
        CONSUME(cb); LOADC(g + 3, cb);
    }

    // ---- Phase B: branchy scan with exact stop bound. ----
    bool done = (ta[KK - 1] >= s_b[PHA - 1]) && (tb[KK - 1] >= s_b[PHA - 1]);
    #pragma unroll 1
    for (int g = PHA; g < NGRP; g += 2) {
        if (!__ballot_sync(0xffffffffu, !done)) break;
        if (!done) {
            CONSUME(ca);
            done = (ta[KK - 1] >= s_b[g]) && (tb[KK - 1] >= s_b[g]);
        }
        if (!done) LOADC(g + 2, ca);
        if (!done) {
            CONSUME(cb);
            done = (ta[KK - 1] >= s_b[g + 1]) && (tb[KK - 1] >= s_b[g + 1]);
        }
        if (!done) LOADC(g + 3, cb);
    }

    // out[m][j][f]: j=0 is x[m][f], j=1..8 are the top values descending.
    size_t bse = (size_t)m0 * ((KK + 1) * FF) + f;
    out[bse] = x[(size_t)m0 * FF + f];
    out[bse + (size_t)(KK + 1) * FF] = x[(size_t)(m0 + 1) * FF + f];
    #pragma unroll
    for (int j = 0; j < KK; j++) {
        out[bse + (size_t)(j + 1) * FF] = ta[j];
        out[bse + (size_t)(KK + 1 + j + 1) * FF] = tb[j];
    }

    #undef LOADC
    #undef INSERT
    #undef CONSUME
}

extern "C" void kernel_launch(void* const* d_in, const int* in_sizes, int n_in,
                              void* d_out, int out_size) {
    const float* x   = (const float*)d_in[0];
    const float* adj = (const float*)d_in[1];
    if (n_in >= 2 && in_sizes[0] > in_sizes[1]) {  // defensive: x is the smaller input
        const float* t = x; x = adj; adj = t;
    }
    float* out = (float*)d_out;

    prep_kernel<<<FF, 256>>>(x);
    topk_kernel<<<dim3(NN / 256, FF), 128>>>(x, adj, out);
}

// round 12
// speedup vs baseline: 1.1051x; 1.1051x over previous
#include <cuda_runtime.h>

#define NN 2048
#define FF 64
#define KK 8
#define GROUP 8
#define NGRP (NN / GROUP)     // 256 groups of 8
#define NROUND (NGRP / 2)     // 128 rounds (2 groups per round, one per parity)
#define RA 6                  // phase-A rounds (12 groups = 96 ranks)
#define SPAD 2080             // s_p entries incl. pipeline-overrun padding
#define NBUCK 4096
#define BSHIFT 20
#define BPT (NBUCK / 256)
#define FULLM 0xffffffffu

// Scratch: per-feature bucket-descending (x value, row byte-offset) pairs +
// exact per-group suffix-max stop bounds.
__device__ float2 g_sp[FF * SPAD];
__device__ float  g_bound[FF * NGRP];

__device__ __forceinline__ unsigned key_of(float v) {
    unsigned u = __float_as_uint(v);
    return (u & 0x80000000u) ? ~u : (u | 0x80000000u);
}
__device__ __forceinline__ float val_of(unsigned k) {
    unsigned u = (k & 0x80000000u) ? (k ^ 0x80000000u) : ~k;
    return __uint_as_float(u);
}

// One block per feature f: counting-sort rows into descending-bucket order,
// emit (x value, row byte-offset) + exact suffix-max bounds.
// Scans use warp shuffles (3 syncs) instead of 32 __syncthreads loops.
__global__ __launch_bounds__(256) void prep_kernel(const float* __restrict__ x) {
    const int tid = threadIdx.x;
    const int f = blockIdx.x;
    const unsigned lane = tid & 31, wrp = tid >> 5;
    const float NEG_INF = -__int_as_float(0x7f800000);

    __shared__ unsigned skey[NN];
    __shared__ int hist[NBUCK];
    __shared__ float sval[NN];
    __shared__ int wsum[8], wsufs[8];
    __shared__ float wmaxs[8], wsufm[8];
    __shared__ float inclmax[256];

    for (int i = tid; i < NBUCK; i += 256) hist[i] = 0;
    __syncthreads();

    // Pass 1: keys + histogram.
    for (int i = tid; i < NN; i += 256) {
        float v = x[(size_t)i * FF + f];
        unsigned k = key_of(v);
        skey[i] = k;
        atomicAdd(&hist[k >> BSHIFT], 1);
    }
    __syncthreads();

    // Pass 2: descending-exclusive bucket offsets via shfl suffix scan.
    const int base = tid * BPT;
    int csum = 0;
    #pragma unroll
    for (int j = 0; j < BPT; j++) csum += hist[base + j];
    int v = csum;
    #pragma unroll
    for (int d = 1; d < 32; d <<= 1) {
        int o = __shfl_down_sync(FULLM, v, d);
        if (lane + d < 32) v += o;        // inclusive suffix sum within warp
    }
    if (lane == 0) wsum[wrp] = v;
    __syncthreads();
    if (tid < 8) {
        int w = wsum[tid];
        #pragma unroll
        for (int d = 1; d < 8; d <<= 1) {
            int o = __shfl_down_sync(0xffu, w, d);
            if (tid + d < 8) w += o;
        }
        wsufs[tid] = w;                    // inclusive suffix over warp totals
    }
    __syncthreads();
    int run = (v - csum) + ((wrp < 7) ? wsufs[wrp + 1] : 0);  // chunks above tid
    #pragma unroll
    for (int j = BPT - 1; j >= 0; j--) {
        int c = hist[base + j];
        hist[base + j] = run;
        run += c;
    }
    __syncthreads();

    // Pass 3: scatter (value, byte offset = idx * NN * 4).
    for (int i = tid; i < NN; i += 256) {
        unsigned k = skey[i];
        float vv = val_of(k);
        int pos = atomicAdd(&hist[k >> BSHIFT], 1);
        g_sp[f * SPAD + pos] = make_float2(vv, __int_as_float(i * (NN * 4)));
        sval[pos] = vv;
    }
    // Padding for pipeline overrun: -inf value, offset 0 (products are -inf
    // or NaN; neither ever enters a top list).
    for (int i = NN + tid; i < SPAD; i += 256)
        g_sp[f * SPAD + i] = make_float2(NEG_INF, __int_as_float(0));
    __syncthreads();

    // Pass 4: exact suffix-max bound per group of 8 (shfl suffix max).
    float gm = NEG_INF;
    #pragma unroll
    for (int j = 0; j < GROUP; j++) gm = fmaxf(gm, sval[tid * GROUP + j]);
    float vm = gm;
    #pragma unroll
    for (int d = 1; d < 32; d <<= 1) {
        float o = __shfl_down_sync(FULLM, vm, d);
        if (lane + d < 32) vm = fmaxf(vm, o);
    }
    if (lane == 0) wmaxs[wrp] = vm;
    __syncthreads();
    if (tid < 8) {
        float w = wmaxs[tid];
        #pragma unroll
        for (int d = 1; d < 8; d <<= 1) {
            float o = __shfl_down_sync(0xffu, w, d);
            if (tid + d < 8) w = fmaxf(w, o);
        }
        wsufm[tid] = w;
    }
    __syncthreads();
    inclmax[tid] = fmaxf(vm, (wrp < 7) ? wsufm[wrp + 1] : NEG_INF);
    __syncthreads();
    // After group g, remaining products <= max(suffix_max(g+1), 0): adj in
    // [0,1) so x>0 -> adj*x <= x, x<=0 -> adj*x <= 0.
    float b = (tid < 255) ? inclmax[tid + 1] : NEG_INF;
    g_bound[f * NGRP + tid] = fmaxf(b, 0.0f);
}

// blockIdx.y = f, blockIdx.x = m-tile of 128. Lane pairs (lane, lane^16)
// share one (m,f): parity 0 scans even groups, parity 1 odd groups, each
// keeping its own sorted top-8. Stop: union-top8 8th best >= max(t7_e,t7_o),
// so fmax(pair t7s) >= s_b[2r+1] is exact. Final bitonic pair-merge.
__global__ __launch_bounds__(256) void topk_kernel(const float* __restrict__ x,
                                                   const float* __restrict__ adj,
                                                   float* __restrict__ out) {
    __shared__ float2 s_p[SPAD];
    __shared__ float  s_b[NGRP];
    const int f = blockIdx.y;
    const int tid = threadIdx.x;
    const float NEG_INF = -__int_as_float(0x7f800000);

    #pragma unroll
    for (int i = tid; i < SPAD; i += 256) s_p[i] = g_sp[f * SPAD + i];
    s_b[tid] = g_bound[f * NGRP + tid];
    __syncthreads();

    const int lane = tid & 31, wid = tid >> 5;
    const int pairid = lane & 15, parity = lane >> 4;
    const int m = blockIdx.x * 128 + wid * 16 + pairid;
    const char* adjm = (const char*)(adj + m);

    float t[KK];
    #pragma unroll
    for (int j = 0; j < KK; j++) t[j] = NEG_INF;

    float ca[GROUP], cb[GROUP];

    // Load the group for round r of this parity: product adj[n][m]*x[n][f].
    #define LOADC(r, buf)                                                     \
        {   const int gg = 2 * (r) + parity;                                  \
            _Pragma("unroll")                                                 \
            for (int u = 0; u < GROUP; u++) {                                 \
                float2 p = s_p[gg * GROUP + u];                               \
                buf[u] = __ldg((const float*)(adjm + __float_as_int(p.y)))    \
                         * p.x;                                               \
            }                                                                 \
        }
    #define CONSUME(buf)                                                      \
        {   _Pragma("unroll")                                                 \
            for (int u = 0; u < GROUP; u++) {                                 \
                float c = buf[u];                                             \
                if (c > t[KK - 1]) {                                          \
                    _Pragma("unroll")                                         \
                    for (int j = 0; j < KK - 1; j++) {                        \
                        float w = fmaxf(t[j], c);                             \
                        c = fminf(t[j], c);                                   \
                        t[j] = w;                                             \
                    }                                                         \
                    t[KK - 1] = fmaxf(t[KK - 1], c);                          \
                }                                                             \
            }                                                                 \
        }

    LOADC(0, ca); LOADC(1, cb);

    // ---- Phase A: rounds 0..RA-1, unconditional, double-buffered. ----
    #pragma unroll
    for (int r = 0; r < RA; r += 2) {
        CONSUME(ca); LOADC(r + 2, ca);
        CONSUME(cb); LOADC(r + 3, cb);
    }

    // ---- Phase B: branchy, exact pair-shared stop bound. ----
    float pt7 = __shfl_xor_sync(FULLM, t[KK - 1], 16);
    bool done = (fmaxf(t[KK - 1], pt7) >= s_b[2 * RA - 1]);
    #pragma unroll 1
    for (int r = RA; r < NROUND; r += 2) {
        if (!__ballot_sync(FULLM, !done)) break;
        if (!done) CONSUME(ca);
        pt7 = __shfl_xor_sync(FULLM, t[KK - 1], 16);
        if (!done) done = (fmaxf(t[KK - 1], pt7) >= s_b[2 * r + 1]);
        if (!done) LOADC(r + 2, ca);
        if (!done) CONSUME(cb);
        pt7 = __shfl_xor_sync(FULLM, t[KK - 1], 16);
        if (!done) done = (fmaxf(t[KK - 1], pt7) >= s_b[2 * r + 3]);
        if (!done) LOADC(r + 3, cb);
    }

    // ---- Pair merge: top-8 of the two sorted-desc 8-lists. ----
    float c[KK];
    #pragma unroll
    for (int j = 0; j < KK; j++) {
        float pv = __shfl_xor_sync(FULLM, t[KK - 1 - j], 16);
        c[j] = fmaxf(t[j], pv);           // bitonic, contains union top-8
    }
    #define CSWP(i, jj)                                                       \
        { float hi = fmaxf(c[i], c[jj]), lo = fminf(c[i], c[jj]);             \
          c[i] = hi; c[jj] = lo; }
    CSWP(0, 4); CSWP(1, 5); CSWP(2, 6); CSWP(3, 7);
    CSWP(0, 2); CSWP(1, 3); CSWP(4, 6); CSWP(5, 7);
    CSWP(0, 1); CSWP(2, 3); CSWP(4, 5); CSWP(6, 7);
    #undef CSWP

    // out[m][j][f]: j=0 is x[m][f], j=1..8 top values descending.
    // Both lanes hold identical c[]; split the 9 stores across the pair.
    size_t bse = (size_t)m * ((KK + 1) * FF) + f;
    if (parity == 0) {
        out[bse] = x[(size_t)m * FF + f];
        #pragma unroll
        for (int j = 0; j < 4; j++) out[bse + (size_t)(j + 1) * FF] = c[j];
    } else {
        #pragma unroll
        for (int j = 4; j < KK; j++) out[bse + (size_t)(j + 1) * FF] = c[j];
    }

    #undef LOADC
    #undef CONSUME
}

extern "C" void kernel_launch(void* const* d_in, const int* in_sizes, int n_in,
                              void* d_out, int out_size) {
    const float* x   = (const float*)d_in[0];
    const float* adj = (const float*)d_in[1];
    if (n_in >= 2 && in_sizes[0] > in_sizes[1]) {  // defensive: x is the smaller input
        const float* t = x; x = adj; adj = t;
    }
    float* out = (float*)d_out;

    prep_kernel<<<FF, 256>>>(x);
    topk_kernel<<<dim3(NN / 128, FF), 256>>>(x, adj, out);
}